// round 10
// baseline (speedup 1.0000x reference)
#include <cuda_runtime.h>
#include <cstdint>

#define E_EDGE 8192
#define BATCH  32
#define N_VAR  2048
#define WARPS  4                         // rows (=warps) per block
#define CHUNK_B  2048                    // bytes per bulk copy
#define CHUNK_F4 (CHUNK_B / 16)          // 128 float4 per chunk
#define SUB      (CHUNK_F4 / 32)         // 4 scan sub-iterations per chunk
#define NCH      ((E_EDGE * 4) / CHUNK_B) // 16 chunks per 32KB row

// scratch: input transposed to [k][b] (1 MB) and llr pre-scaled+transposed to [v][b] (256 KB)
__device__ float g_inputT[E_EDGE * BATCH];
__device__ float g_llrT[N_VAR * BATCH];

__global__ __launch_bounds__(256) void prep_kernel(const float* __restrict__ input,
                                                   const float* __restrict__ llr,
                                                   const float* __restrict__ llr_w) {
    int tid = blockIdx.x * blockDim.x + threadIdx.x;
    if (tid < E_EDGE * BATCH) {
        int b = tid >> 13;           // tid / 8192  (coalesced read along k)
        int k = tid & (E_EDGE - 1);
        g_inputT[k * BATCH + b] = input[tid];
    } else {
        int t = tid - E_EDGE * BATCH;
        if (t < N_VAR * BATCH) {
            int b = t >> 11;         // t / 2048
            int v = t & (N_VAR - 1);
            g_llrT[v * BATCH + b] = llr[t] * llr_w[v];
        }
    }
}

__device__ __forceinline__ unsigned su32(const void* p) {
    unsigned a;
    asm("{ .reg .u64 t; cvta.to.shared.u64 t, %1; cvt.u32.u64 %0, t; }" : "=r"(a) : "l"(p));
    return a;
}

__device__ __forceinline__ void mbar_wait(unsigned mb, unsigned par) {
    unsigned ok;
    do {
        asm volatile("{\n\t.reg .pred p;\n\t"
                     "mbarrier.try_wait.parity.acquire.cta.shared::cta.b64 p, [%1], %2, 0x989680;\n\t"
                     "selp.b32 %0, 1, 0, p;\n\t}"
                     : "=r"(ok) : "r"(mb), "r"(par) : "memory");
    } while (!ok);
}

__device__ __forceinline__ void issue_bulk(unsigned dst, const char* src, unsigned mb) {
    asm volatile("mbarrier.arrive.expect_tx.shared.b64 _, [%0], %1;"
                 :: "r"(mb), "r"((unsigned)CHUNK_B) : "memory");
    asm volatile("cp.async.bulk.shared::cta.global.mbarrier::complete_tx::bytes [%0], [%1], %2, [%3];"
                 :: "r"(dst), "l"(src), "r"((unsigned)CHUNK_B), "r"(mb) : "memory");
}

// One warp per output row; lane = batch b. The 256MB mask stream flows through a
// per-warp 2-stage x 2KB cp.async.bulk ring: in-flight bytes live in the async
// engine + smem (not registers), so KB-in-flight/SM (~200KB) is decoupled from
// occupancy/registers — the binding resource identified across R3-R9.
// Weight is never streamed (mask*weight == 0 wherever mask == 0 for ANY weight);
// it is gathered as one float4 per hit (~8 hits/row).
__global__ __launch_bounds__(128) void bp_main_kernel(
    const float* __restrict__ mask,
    const float* __restrict__ weight,
    float* __restrict__ out)
{
    __shared__ __align__(16) float4 buf[WARPS][2][CHUNK_F4];   // 16 KB
    __shared__ float tile[WARPS][33];
    __shared__ __align__(8) unsigned long long mbar[WARPS][2];

    const int warp = threadIdx.x >> 5;
    const int lane = threadIdx.x & 31;          // batch b
    const int row0 = blockIdx.x * WARPS;
    const int row  = row0 + warp;               // e_out

    const char*  src0 = (const char*)(mask + (size_t)row * E_EDGE);
    const float* wr   = weight + (size_t)row * E_EDGE;

    const unsigned mb0 = su32(&mbar[warp][0]);
    const unsigned mb1 = su32(&mbar[warp][1]);
    const unsigned bf0 = su32(&buf[warp][0][0]);
    const unsigned bf1 = su32(&buf[warp][1][0]);

    if (lane == 0) {
        asm volatile("mbarrier.init.shared.b64 [%0], 1;" :: "r"(mb0) : "memory");
        asm volatile("mbarrier.init.shared.b64 [%0], 1;" :: "r"(mb1) : "memory");
        asm volatile("fence.proxy.async.shared::cta;" ::: "memory");
        // prologue: chunks 0 and 1 in flight
        issue_bulk(bf0, src0, mb0);
        issue_bulk(bf1, src0 + CHUNK_B, mb1);
    }
    __syncwarp();

    float acc = 0.0f;

    for (int c = 0; c < NCH; ++c) {
        const int s = c & 1;
        const unsigned mb = s ? mb1 : mb0;
        mbar_wait(mb, (c >> 1) & 1);

        const float4* cbuf = buf[warp][s];
        #pragma unroll
        for (int i = 0; i < SUB; ++i) {
            float4 m = cbuf[i * 32 + lane];                      // LDS.128, conflict-free
            // integer nz test; <<1 drops sign bit so ±0.0 is skipped (exact)
            unsigned bits = (__float_as_uint(m.x) | __float_as_uint(m.y) |
                             __float_as_uint(m.z) | __float_as_uint(m.w)) << 1;
            unsigned ball = __ballot_sync(0xFFFFFFFFu, bits != 0u);

            // rare path: ~8 nonzeros per whole row of 8192
            while (ball) {
                int sl = __ffs(ball) - 1;
                ball &= ball - 1;
                float mx = __shfl_sync(0xFFFFFFFFu, m.x, sl);
                float my = __shfl_sync(0xFFFFFFFFu, m.y, sl);
                float mz = __shfl_sync(0xFFFFFFFFu, m.z, sl);
                float mw = __shfl_sync(0xFFFFFFFFu, m.w, sl);
                const int k0 = c * (CHUNK_B / 4) + i * 128 + sl * 4;
                const float4 w4 = __ldg(reinterpret_cast<const float4*>(wr + k0)); // one 16B gather
                const float* t = g_inputT + (size_t)k0 * BATCH + lane;             // coalesced
                if (mx != 0.0f) acc = fmaf(mx * w4.x, t[0 * BATCH], acc);
                if (my != 0.0f) acc = fmaf(my * w4.y, t[1 * BATCH], acc);
                if (mz != 0.0f) acc = fmaf(mz * w4.z, t[2 * BATCH], acc);
                if (mw != 0.0f) acc = fmaf(mw * w4.w, t[3 * BATCH], acc);
            }
        }

        // refill this stage for chunk c+2 (values above already consumed; the
        // last ballot converged the warp, and the bulk write cannot land before
        // the ~300cyc L2 round-trip, far after the 29cyc LDS reads complete)
        const int nxt = c + 2;
        if (nxt < NCH && lane == 0)
            issue_bulk(s ? bf1 : bf0, src0 + (size_t)nxt * CHUNK_B, mb);
        __syncwarp();
    }

    // epilogue: llr term (pre-scaled, coalesced) + smem transpose
    tile[warp][lane] = 0.5f * (g_llrT[(row & (N_VAR - 1)) * BATCH + lane] + acc);
    __syncthreads();

    // thread t: b = t>>2 (0..31), el = t&3 -> 16B aligned stores per 4-thread group
    const int b  = threadIdx.x >> 2;
    const int el = threadIdx.x & 3;
    out[(size_t)b * E_EDGE + row0 + el] = tile[el][b];
}

extern "C" void kernel_launch(void* const* d_in, const int* in_sizes, int n_in,
                              void* d_out, int out_size) {
    const float* input    = (const float*)d_in[0];  // [32, 8192]
    const float* input_w  = (const float*)d_in[1];  // [8192, 8192]
    const float* mask     = (const float*)d_in[2];  // [8192, 8192]
    const float* llr      = (const float*)d_in[3];  // [32, 2048]
    const float* llr_w    = (const float*)d_in[4];  // [1, 2048]
    // d_in[5] = llr_expander (one-hot of e % N_VAR) — realized via index math
    float* out = (float*)d_out;                     // [32, 8192]

    (void)in_sizes; (void)n_in; (void)out_size;

    const int prep_n = E_EDGE * BATCH + N_VAR * BATCH;
    prep_kernel<<<(prep_n + 255) / 256, 256>>>(input, llr, llr_w);

    // 8192 rows, 4 rows (warps) per 128-thread block
    bp_main_kernel<<<E_EDGE / WARPS, 128>>>(mask, input_w, out);
}

// round 11
// speedup vs baseline: 1.1897x; 1.1897x over previous
#include <cuda_runtime.h>

#define E_EDGE 8192
#define BATCH  32
#define N_VAR  2048

// scratch: input transposed to [k][b] (1 MB) and llr pre-scaled+transposed to [v][b] (256 KB)
__device__ float g_inputT[E_EDGE * BATCH];
__device__ float g_llrT[N_VAR * BATCH];

__global__ __launch_bounds__(256) void prep_kernel(const float* __restrict__ input,
                                                   const float* __restrict__ llr,
                                                   const float* __restrict__ llr_w) {
    int tid = blockIdx.x * blockDim.x + threadIdx.x;
    if (tid < E_EDGE * BATCH) {
        int b = tid >> 13;           // tid / 8192  (coalesced read along k)
        int k = tid & (E_EDGE - 1);
        g_inputT[k * BATCH + b] = input[tid];
    } else {
        int t = tid - E_EDGE * BATCH;
        if (t < N_VAR * BATCH) {
            int b = t >> 11;         // t / 2048
            int v = t & (N_VAR - 1);
            g_llrT[v * BATCH + b] = llr[t] * llr_w[v];
        }
    }
}

// One warp per output row e_out; lane = batch b.
// Weight is never streamed (mask*weight == 0 wherever mask == 0, for ANY
// weight); it's gathered as one float4 per hit (~8 hits/row of 8192).
// KEY CHANGE (R11): DRAM-side MLP is supplied by prefetch.global.L2 — each
// group issues one predicated prefetch instruction covering the 2KB group two
// iterations ahead. Prefetches consume no registers/scoreboards/smem, so
// outstanding DRAM bytes/SM are no longer capped by the register file (the
// binding resource identified across R3-R10). Demand loads then hit L2.
__global__ __launch_bounds__(256, 6) void bp_main_kernel(
    const float* __restrict__ mask,
    const float* __restrict__ weight,
    float* __restrict__ out)
{
    const int warp = threadIdx.x >> 5;          // 0..7
    const int lane = threadIdx.x & 31;          // batch b
    const int row0 = blockIdx.x << 3;           // 8 rows per block
    const int row  = row0 + warp;               // e_out

    const float4* __restrict__ m4 = reinterpret_cast<const float4*>(mask + (size_t)row * E_EDGE);
    const float*  __restrict__ wr = weight + (size_t)row * E_EDGE;
    const char*   rbase = (const char*)m4;

    float acc = 0.0f;

    // prologue: prefetch groups 0 and 1 (4KB) so the first demand loads hit L2
    if (lane < 16) {
        asm volatile("prefetch.global.L2 [%0];" :: "l"(rbase + lane * 128));
        asm volatile("prefetch.global.L2 [%0];" :: "l"(rbase + 2048 + lane * 128));
    }

    // 16 groups × (4 chunks × 32 lanes × 4 floats) = 8192
    const int NG = E_EDGE / 512;
    for (int g = 0; g < NG; ++g) {
        // prefetch group g+2 (one 128B line per lane 0..15 = 2KB, 1 warp instr)
        if (g + 2 < NG && lane < 16)
            asm volatile("prefetch.global.L2 [%0];"
                         :: "l"(rbase + (size_t)(g + 2) * 2048 + lane * 128));

        float4 m[4];
        #pragma unroll
        for (int it = 0; it < 4; ++it)
            m[it] = __ldcs(&m4[(g * 4 + it) * 32 + lane]);

        #pragma unroll
        for (int it = 0; it < 4; ++it) {
            // integer nz test; <<1 drops sign bit so ±0.0 is skipped (exact)
            unsigned bits = (__float_as_uint(m[it].x) | __float_as_uint(m[it].y) |
                             __float_as_uint(m[it].z) | __float_as_uint(m[it].w)) << 1;
            unsigned ball = __ballot_sync(0xFFFFFFFFu, bits != 0u);

            // rare path: ~8 nonzeros per whole row of 8192
            while (ball) {
                int src = __ffs(ball) - 1;
                ball &= ball - 1;
                float mx = __shfl_sync(0xFFFFFFFFu, m[it].x, src);
                float my = __shfl_sync(0xFFFFFFFFu, m[it].y, src);
                float mz = __shfl_sync(0xFFFFFFFFu, m[it].z, src);
                float mw = __shfl_sync(0xFFFFFFFFu, m[it].w, src);
                const int k0 = (g * 4 + it) * 128 + src * 4;
                const float4 w4 = __ldg(reinterpret_cast<const float4*>(wr + k0));
                const float* t = g_inputT + (size_t)k0 * BATCH + lane;  // coalesced
                if (mx != 0.0f) acc = fmaf(mx * w4.x, t[0 * BATCH], acc);
                if (my != 0.0f) acc = fmaf(my * w4.y, t[1 * BATCH], acc);
                if (mz != 0.0f) acc = fmaf(mz * w4.z, t[2 * BATCH], acc);
                if (mw != 0.0f) acc = fmaf(mw * w4.w, t[3 * BATCH], acc);
            }
        }
    }

    // epilogue: llr term (pre-scaled, coalesced) + smem transpose for full-sector stores
    __shared__ float tile[8][33];
    tile[warp][lane] = 0.5f * (g_llrT[(row & (N_VAR - 1)) * BATCH + lane] + acc);
    __syncthreads();

    // thread t: b = t>>3 (0..31), el = t&7 -> each 8-thread group writes one
    // full, aligned 32B sector of out[b][row0 .. row0+7]
    const int b  = threadIdx.x >> 3;
    const int el = threadIdx.x & 7;
    out[(size_t)b * E_EDGE + row0 + el] = tile[el][b];
}

extern "C" void kernel_launch(void* const* d_in, const int* in_sizes, int n_in,
                              void* d_out, int out_size) {
    const float* input    = (const float*)d_in[0];  // [32, 8192]
    const float* input_w  = (const float*)d_in[1];  // [8192, 8192]
    const float* mask     = (const float*)d_in[2];  // [8192, 8192]
    const float* llr      = (const float*)d_in[3];  // [32, 2048]
    const float* llr_w    = (const float*)d_in[4];  // [1, 2048]
    // d_in[5] = llr_expander (one-hot of e % N_VAR) — realized via index math
    float* out = (float*)d_out;                     // [32, 8192]

    (void)in_sizes; (void)n_in; (void)out_size;

    const int prep_n = E_EDGE * BATCH + N_VAR * BATCH;
    prep_kernel<<<(prep_n + 255) / 256, 256>>>(input, llr, llr_w);

    // 8192 rows, 8 rows (warps) per 256-thread block
    bp_main_kernel<<<E_EDGE / 8, 256>>>(mask, input_w, out);
}